// round 6
// baseline (speedup 1.0000x reference)
#include <cuda_runtime.h>
#include <cstdint>
#include <cstddef>

// ---------------------------------------------------------------------------
// ModularTreeMLPPredictor: D=11 level-sequential tree MLP.
//   x = [features(32) | left | right | treatment] (K1=35)
//   h = relu(x@W1+b1) (35->64); h2 = relu(h@W2+b2) (64->64); y = h2@W3+b3.
//
// R5 finding: 2 CTAs/SM (92.7KB smem) = 22% occ -> fma pipe only 28% busy.
// R5 fix: TM 128->64 and single activation h-buffer (h2 overwrites h in
// place after a barrier; accs hold h2 in regs) -> 52.3KB/CTA -> 3 CTAs/SM.
//
// Math core unchanged: weights in smem, activations TRANSPOSED ([k][row],
// STRIDE=TM+2), packed fma.rn.f32x2 (FFMA2, 2x fp32 rate, PTX-only).
// STRIDE == 2 mod 8: 4-way (not 8-way) conflicts on column-strided STS.64.
// ---------------------------------------------------------------------------

#define DLEV   11
#define BATCH  512
#define NNODES 2047
#define FDIM   32
#define HDIM   64
#define K1     35

typedef unsigned long long u64;

__device__ __forceinline__ u64 dup_f(float x) {
    u64 r;
    asm("mov.b64 %0, {%1, %1};" : "=l"(r) : "r"(__float_as_uint(x)));
    return r;
}
__device__ __forceinline__ void ffma2(u64 &d, u64 a, u64 b) {
    asm("fma.rn.f32x2 %0, %1, %2, %0;" : "+l"(d) : "l"(a), "l"(b));
}
__device__ __forceinline__ u64 relu2(u64 v) {
    float lo = __uint_as_float((unsigned)(v & 0xffffffffull));
    float hi = __uint_as_float((unsigned)(v >> 32));
    lo = fmaxf(lo, 0.f);
    hi = fmaxf(hi, 0.f);
    return ((u64)__float_as_uint(hi) << 32) | (u64)__float_as_uint(lo);
}

// smem float layout (dynamic):
//   W1s[2240] | b1s[64] | W2s[4096] | b2s[64] | W3s[64] | b3s[8]
//   xbuf[K1*STRIDE] | hbuf[HDIM*STRIDE] | (tail only) ybuf[66]
#define WOFF (K1*HDIM + HDIM + HDIM*HDIM + HDIM + HDIM + 8)  // 6536 floats

// ---- 3-layer MLP engine on a TM-row transposed tile ----
// x in xbuf[k][r] (k<K1). h/h2 live in hbuf (h2 overwrites h in place).
template <int TM>
__device__ __forceinline__ void mlp_layers12(const float* xbuf, float* hbuf,
                                             const float* W1s, const float* b1s,
                                             const float* W2s, const float* b2s,
                                             int r0, int c0)
{
    constexpr int STRIDE = TM + 2;
    constexpr int PAIRS  = TM / 32;

    // layer 1: xbuf -> hbuf (disjoint buffers; no pre-barrier needed)
    {
        u64 acc[PAIRS][4];
        #pragma unroll
        for (int j = 0; j < 4; j++) {
            u64 bb = dup_f(b1s[c0 + j]);
            #pragma unroll
            for (int p = 0; p < PAIRS; p++) acc[p][j] = bb;
        }
        #pragma unroll 7
        for (int k = 0; k < K1; k++) {
            const u64* arow = (const u64*)(xbuf + k * STRIDE + r0);
            u64 a[PAIRS];
            #pragma unroll
            for (int p = 0; p < PAIRS; p++) a[p] = arow[p];
            float4 w4 = *(const float4*)(W1s + k * HDIM + c0);
            u64 bj0 = dup_f(w4.x), bj1 = dup_f(w4.y);
            u64 bj2 = dup_f(w4.z), bj3 = dup_f(w4.w);
            #pragma unroll
            for (int p = 0; p < PAIRS; p++) {
                ffma2(acc[p][0], a[p], bj0);
                ffma2(acc[p][1], a[p], bj1);
                ffma2(acc[p][2], a[p], bj2);
                ffma2(acc[p][3], a[p], bj3);
            }
        }
        #pragma unroll
        for (int j = 0; j < 4; j++)
            #pragma unroll
            for (int p = 0; p < PAIRS; p++)
                *(u64*)(hbuf + (c0 + j) * STRIDE + r0 + 2 * p) = relu2(acc[p][j]);
    }
    __syncthreads();   // h complete & visible

    // layer 2: read ALL of hbuf into accs, barrier, then overwrite with h2
    {
        u64 acc[PAIRS][4];
        #pragma unroll
        for (int j = 0; j < 4; j++) {
            u64 bb = dup_f(b2s[c0 + j]);
            #pragma unroll
            for (int p = 0; p < PAIRS; p++) acc[p][j] = bb;
        }
        #pragma unroll 8
        for (int k = 0; k < HDIM; k++) {
            const u64* arow = (const u64*)(hbuf + k * STRIDE + r0);
            u64 a[PAIRS];
            #pragma unroll
            for (int p = 0; p < PAIRS; p++) a[p] = arow[p];
            float4 w4 = *(const float4*)(W2s + k * HDIM + c0);
            u64 bj0 = dup_f(w4.x), bj1 = dup_f(w4.y);
            u64 bj2 = dup_f(w4.z), bj3 = dup_f(w4.w);
            #pragma unroll
            for (int p = 0; p < PAIRS; p++) {
                ffma2(acc[p][0], a[p], bj0);
                ffma2(acc[p][1], a[p], bj1);
                ffma2(acc[p][2], a[p], bj2);
                ffma2(acc[p][3], a[p], bj3);
            }
        }
        __syncthreads();   // everyone done READING h
        #pragma unroll
        for (int j = 0; j < 4; j++)
            #pragma unroll
            for (int p = 0; p < PAIRS; p++)
                *(u64*)(hbuf + (c0 + j) * STRIDE + r0 + 2 * p) = relu2(acc[p][j]);
    }
    __syncthreads();   // h2 complete & visible
}

// layer 3 dot: 4-way split (row = tid>>2, quarter = tid&3), shfl-combined.
template <int TM>
__device__ __forceinline__ float mlp_layer3(const float* hbuf, const float* W3s,
                                            int tid)
{
    constexpr int STRIDE = TM + 2;
    const int row = tid >> 2;
    const int qt  = tid & 3;
    float y = 0.f;
    if (row < TM) {
        const float* col = hbuf + qt * 16 * STRIDE + row;
        const float* w   = W3s + qt * 16;
        #pragma unroll 8
        for (int c = 0; c < 16; c++)
            y = fmaf(col[c * STRIDE], w[c], y);
    }
    y += __shfl_xor_sync(0xffffffffu, y, 1);
    y += __shfl_xor_sync(0xffffffffu, y, 2);
    return y;   // valid for qt==0, row<TM
}

// ---------------- big levels (l >= 6): one launch per level ----------------
template <int TM>
__global__ void __launch_bounds__(256, 3)
level_kernel(const float* __restrict__ features,
             const float* __restrict__ treatment,
             float* __restrict__ out,
             const float* __restrict__ W1, const float* __restrict__ b1,
             const float* __restrict__ W2, const float* __restrict__ b2,
             const float* __restrict__ W3, const float* __restrict__ b3,
             int lshift, int leaf)
{
    constexpr int STRIDE = TM + 2;
    const int n     = 1 << lshift;
    const int start = n - 1;

    extern __shared__ float sm[];
    float* W1s  = sm;
    float* b1s  = W1s + K1 * HDIM;
    float* W2s  = b1s + HDIM;
    float* b2s  = W2s + HDIM * HDIM;
    float* W3s  = b2s + HDIM;
    float* b3s  = W3s + HDIM;
    float* xbuf = sm + WOFF;
    float* hbuf = xbuf + K1 * STRIDE;

    const int tid = threadIdx.x;

    for (int i = tid; i < K1 * HDIM; i += 256)   W1s[i] = W1[i];
    for (int i = tid; i < HDIM * HDIM; i += 256) W2s[i] = W2[i];
    if (tid < HDIM) {
        b1s[tid] = b1[tid];
        b2s[tid] = b2[tid];
        W3s[tid] = W3[tid];
    }
    if (tid == 0) b3s[0] = b3[0];

    const int row0 = blockIdx.x * TM;
    for (int i = tid; i < TM * (FDIM / 4); i += 256) {
        int r = i >> 3;
        int q = i & 7;
        int g = row0 + r;
        int b = g >> lshift;
        int node = g & (n - 1);
        float4 v = *(const float4*)
            (features + ((size_t)b * NNODES + start + node) * FDIM + 4 * q);
        xbuf[(4 * q + 0) * STRIDE + r] = v.x;
        xbuf[(4 * q + 1) * STRIDE + r] = v.y;
        xbuf[(4 * q + 2) * STRIDE + r] = v.z;
        xbuf[(4 * q + 3) * STRIDE + r] = v.w;
    }
    if (tid < TM) {
        int g = row0 + tid;
        int b = g >> lshift;
        int node = g & (n - 1);
        float lv = 0.f, rv = 0.f;
        if (!leaf) {
            const float* c = out + (size_t)b * NNODES + (2 * n - 1) + 2 * node;
            lv = c[0];
            rv = c[1];
        }
        xbuf[32 * STRIDE + tid] = lv;
        xbuf[33 * STRIDE + tid] = rv;
        xbuf[34 * STRIDE + tid] = treatment[b];
    }
    __syncthreads();

    const int r0 = (tid >> 4) * (TM / 16);
    const int c0 = (tid & 15) * 4;
    mlp_layers12<TM>(xbuf, hbuf, W1s, b1s, W2s, b2s, r0, c0);

    float y = mlp_layer3<TM>(hbuf, W3s, tid);
    const int row = tid >> 2;
    if ((tid & 3) == 0 && row < TM) {
        int g = row0 + row;
        int b = g >> lshift;
        int node = g & (n - 1);
        out[(size_t)b * NNODES + start + node] = y + b3s[0];
    }
}

// ------------- tail levels (l = 5..0): one launch, 512 blocks -------------
__global__ void __launch_bounds__(256, 3)
tail_kernel(const float* __restrict__ features,
            const float* __restrict__ treatment,
            float* __restrict__ out,
            const float* __restrict__ W1, const float* __restrict__ b1,
            const float* __restrict__ W2, const float* __restrict__ b2,
            const float* __restrict__ W3, const float* __restrict__ b3)
{
    constexpr int TM     = 32;
    constexpr int STRIDE = TM + 2;

    extern __shared__ float sm[];
    float* W1s  = sm;
    float* b1s  = W1s + K1 * HDIM;
    float* W2s  = b1s + HDIM;
    float* b2s  = W2s + HDIM * HDIM;
    float* W3s  = b2s + HDIM;
    float* b3s  = W3s + HDIM;
    float* xbuf = sm + WOFF;
    float* hbuf = xbuf + K1 * STRIDE;
    float* ybuf = hbuf + HDIM * STRIDE;   // 66 floats: child values

    const int tid = threadIdx.x;
    const int b   = blockIdx.x;
    const float tval = treatment[b];

    // preload level-6 outputs (children of level 5): out[b*2047 + 63..126]
    if (tid < 64)
        ybuf[tid] = out[(size_t)b * NNODES + 63 + tid];

    const int r0 = (tid >> 4) * (TM / 16);   // 2 rows/thread
    const int c0 = (tid & 15) * 4;

    for (int l = 5; l >= 0; --l) {
        const int n     = 1 << l;
        const int start = n - 1;
        const float* w1l = W1 + (size_t)l * K1 * HDIM;
        const float* b1l = b1 + (size_t)l * HDIM;
        const float* w2l = W2 + (size_t)l * HDIM * HDIM;
        const float* b2l = b2 + (size_t)l * HDIM;
        const float* w3l = W3 + (size_t)l * HDIM;
        const float* b3l = b3 + (size_t)l;

        __syncthreads();   // prior level fully done (ybuf, weight reads)

        for (int i = tid; i < K1 * HDIM; i += 256)   W1s[i] = w1l[i];
        for (int i = tid; i < HDIM * HDIM; i += 256) W2s[i] = w2l[i];
        if (tid < HDIM) {
            b1s[tid] = b1l[tid];
            b2s[tid] = b2l[tid];
            W3s[tid] = w3l[tid];
        }
        if (tid == 0) b3s[0] = b3l[0];

        for (int i = tid; i < n * (FDIM / 4); i += 256) {
            int r = i >> 3;
            int q = i & 7;
            float4 v = *(const float4*)
                (features + ((size_t)b * NNODES + start + r) * FDIM + 4 * q);
            xbuf[(4 * q + 0) * STRIDE + r] = v.x;
            xbuf[(4 * q + 1) * STRIDE + r] = v.y;
            xbuf[(4 * q + 2) * STRIDE + r] = v.z;
            xbuf[(4 * q + 3) * STRIDE + r] = v.w;
        }
        if (tid < n) {
            xbuf[32 * STRIDE + tid] = ybuf[2 * tid];
            xbuf[33 * STRIDE + tid] = ybuf[2 * tid + 1];
            xbuf[34 * STRIDE + tid] = tval;
        }
        __syncthreads();

        mlp_layers12<TM>(xbuf, hbuf, W1s, b1s, W2s, b2s, r0, c0);

        float y = mlp_layer3<TM>(hbuf, W3s, tid);
        const int row = tid >> 2;
        if ((tid & 3) == 0 && row < n) {
            float yo = y + b3s[0];
            ybuf[row] = yo;
            out[(size_t)b * NNODES + start + row] = yo;
        }
    }
}

extern "C" void kernel_launch(void* const* d_in, const int* in_sizes, int n_in,
                              void* d_out, int out_size)
{
    const float* features  = (const float*)d_in[0];
    const float* treatment = (const float*)d_in[1];
    const float* W1 = (const float*)d_in[2];
    const float* b1 = (const float*)d_in[3];
    const float* W2 = (const float*)d_in[4];
    const float* b2 = (const float*)d_in[5];
    const float* W3 = (const float*)d_in[6];
    const float* b3 = (const float*)d_in[7];
    float* out = (float*)d_out;

    // TM=64: 6536 + 35*66 + 64*66 = 13070 floats = 52,280 B -> 3 CTAs/SM
    const int smem64   = (WOFF + K1 * 66 + HDIM * 66) * 4;
    // tail TM=32: 6536 + 35*34 + 64*34 + 66 = 9968 floats = 39,872 B
    const int smemTail = (WOFF + K1 * 34 + HDIM * 34 + 66) * 4;
    cudaFuncSetAttribute(level_kernel<64>,
                         cudaFuncAttributeMaxDynamicSharedMemorySize, smem64);
    cudaFuncSetAttribute(tail_kernel,
                         cudaFuncAttributeMaxDynamicSharedMemorySize, smemTail);

    for (int l = DLEV - 1; l >= 6; --l) {
        const int rows = BATCH << l;
        const int leaf = (l == DLEV - 1) ? 1 : 0;
        level_kernel<64><<<rows / 64, 256, smem64>>>(
            features, treatment, out,
            W1 + (size_t)l * K1 * HDIM, b1 + (size_t)l * HDIM,
            W2 + (size_t)l * HDIM * HDIM, b2 + (size_t)l * HDIM,
            W3 + (size_t)l * HDIM, b3 + (size_t)l,
            l, leaf);
    }
    tail_kernel<<<BATCH, 256, smemTail>>>(
        features, treatment, out, W1, b1, W2, b2, W3, b3);
}

// round 13
// speedup vs baseline: 1.1300x; 1.1300x over previous
#include <cuda_runtime.h>
#include <cstdint>
#include <cstddef>

// ---------------------------------------------------------------------------
// ModularTreeMLPPredictor: D=11 level-sequential tree MLP.
//   x = [features(32)|left|right|treatment] (K1=35)
//   h = relu(x@W1+b1) 35->64; h2 = relu(h@W2+b2) 64->64; y = h2@W3+b3.
//
// R6 finding: fma 26% / issue 30% at occ 34% -> latency-stalled LDS->FFMA2
// chains, not warp-count starvation.
// Engine (R7..R12, unchanged since R9): thread tile 8 rows x CT cols
// (warp-uniform A broadcast), software-pipelined k-loop (branchless rotate:
// KK-1 iters + tail), A rows via LDS.128 (ulonglong2), epilogue via
// STS.128, float2 weight prefetch (CT=2), ST=TM+4 alignment. FFMA2
// (fma.rn.f32x2, PTX-only) math engine: 8 of ~13 issue slots per k-iter.
// ---------------------------------------------------------------------------

#define DLEV   11
#define BATCH  512
#define NNODES 2047
#define FDIM   32
#define HDIM   64
#define K1     35

typedef unsigned long long u64;

__device__ __forceinline__ u64 dup_f(float x) {
    u64 r;
    asm("mov.b64 %0, {%1, %1};" : "=l"(r) : "r"(__float_as_uint(x)));
    return r;
}
__device__ __forceinline__ void ffma2(u64 &d, u64 a, u64 b) {
    asm("fma.rn.f32x2 %0, %1, %2, %0;" : "+l"(d) : "l"(a), "l"(b));
}
__device__ __forceinline__ u64 relu2(u64 v) {
    float lo = __uint_as_float((unsigned)(v & 0xffffffffull));
    float hi = __uint_as_float((unsigned)(v >> 32));
    lo = fmaxf(lo, 0.f);
    hi = fmaxf(hi, 0.f);
    return ((u64)__float_as_uint(hi) << 32) | (u64)__float_as_uint(lo);
}

// smem float layout (dynamic):
//   W1s[2240] | b1s[64] | W2s[4096] | b2s[64] | W3s[64] | b3s[8]
//   xbuf[K1*ST] | hbuf[HDIM*ST] | (tail only) ybuf[66]
#define WOFF (K1*HDIM + HDIM + HDIM*HDIM + HDIM + HDIM + 8)  // 6536 floats

// ---- one GEMM layer: buf_in (KK rows, transposed [k][row]) -> acc ----
// Thread tile: 8 rows (4 f32x2 pairs) x CT cols. r0 is warp-uniform, so the
// two 16B A loads per k are warp-broadcast (conflict-free).
template <int TM, int KK, int CT>
__device__ __forceinline__ void gemm_accum(const float* __restrict__ bin,
                                           const float* __restrict__ Ws,
                                           const float* __restrict__ bs,
                                           int r0, int c0, u64 acc[4][CT])
{
    constexpr int ST = TM + 4;

    #pragma unroll
    for (int j = 0; j < CT; j++) {
        u64 bb = dup_f(bs[c0 + j]);
        #pragma unroll
        for (int p = 0; p < 4; p++) acc[p][j] = bb;
    }

    ulonglong2 a0_cur, a1_cur;
    float w_cur[CT];

    // prefetch k = 0
    {
        const ulonglong2* ar = (const ulonglong2*)(bin + r0);
        a0_cur = ar[0];
        a1_cur = ar[1];
        if constexpr (CT == 2) {
            float2 w2 = *(const float2*)(Ws + c0);
            w_cur[0] = w2.x; w_cur[1] = w2.y;
        } else {
            #pragma unroll
            for (int j = 0; j < CT; j++) w_cur[j] = Ws[c0 + j];
        }
    }

    // branchless rotate: KK-1 steps of {load k+1, fma k, rotate}
    #pragma unroll 8
    for (int k = 0; k < KK - 1; k++) {
        ulonglong2 a0_nxt, a1_nxt;
        float w_nxt[CT];
        {
            const ulonglong2* ar = (const ulonglong2*)(bin + (k + 1) * ST + r0);
            a0_nxt = ar[0];
            a1_nxt = ar[1];
            if constexpr (CT == 2) {
                float2 w2 = *(const float2*)(Ws + (k + 1) * HDIM + c0);
                w_nxt[0] = w2.x; w_nxt[1] = w2.y;
            } else {
                #pragma unroll
                for (int j = 0; j < CT; j++) w_nxt[j] = Ws[(k + 1) * HDIM + c0 + j];
            }
        }
        #pragma unroll
        for (int j = 0; j < CT; j++) {
            u64 wd = dup_f(w_cur[j]);
            ffma2(acc[0][j], a0_cur.x, wd);
            ffma2(acc[1][j], a0_cur.y, wd);
            ffma2(acc[2][j], a1_cur.x, wd);
            ffma2(acc[3][j], a1_cur.y, wd);
        }
        a0_cur = a0_nxt;
        a1_cur = a1_nxt;
        #pragma unroll
        for (int j = 0; j < CT; j++) w_cur[j] = w_nxt[j];
    }
    // tail: k = KK-1
    #pragma unroll
    for (int j = 0; j < CT; j++) {
        u64 wd = dup_f(w_cur[j]);
        ffma2(acc[0][j], a0_cur.x, wd);
        ffma2(acc[1][j], a0_cur.y, wd);
        ffma2(acc[2][j], a1_cur.x, wd);
        ffma2(acc[3][j], a1_cur.y, wd);
    }
}

// Layers 1+2 on a TM-row tile. x in xbuf[k][r]; h2 ends up in hbuf.
template <int TM>
__device__ __forceinline__ void mlp_layers12(const float* xbuf, float* hbuf,
                                             const float* W1s, const float* b1s,
                                             const float* W2s, const float* b2s,
                                             int tid)
{
    constexpr int ST = TM + 4;
    constexpr int CT = TM / 32;              // 2 for TM=64, 1 for TM=32
    constexpr int CG = 64 / CT;              // col-groups (32 or 64)
    const int r0 = (tid / CG) * 8;
    const int c0 = (tid % CG) * CT;

    u64 acc[4][CT];

    // layer 1: xbuf -> hbuf
    gemm_accum<TM, K1, CT>(xbuf, W1s, b1s, r0, c0, acc);
    #pragma unroll
    for (int j = 0; j < CT; j++) {
        ulonglong2* d = (ulonglong2*)(hbuf + (c0 + j) * ST + r0);
        d[0] = make_ulonglong2(relu2(acc[0][j]), relu2(acc[1][j]));
        d[1] = make_ulonglong2(relu2(acc[2][j]), relu2(acc[3][j]));
    }
    __syncthreads();   // h complete

    // layer 2: hbuf -> regs -> overwrite hbuf in place
    gemm_accum<TM, HDIM, CT>(hbuf, W2s, b2s, r0, c0, acc);
    __syncthreads();   // all reads of h done
    #pragma unroll
    for (int j = 0; j < CT; j++) {
        ulonglong2* d = (ulonglong2*)(hbuf + (c0 + j) * ST + r0);
        d[0] = make_ulonglong2(relu2(acc[0][j]), relu2(acc[1][j]));
        d[1] = make_ulonglong2(relu2(acc[2][j]), relu2(acc[3][j]));
    }
    __syncthreads();   // h2 complete
}

// layer 3 dot: 4-way split (row = tid>>2, quarter = tid&3), shfl-combined.
template <int TM>
__device__ __forceinline__ float mlp_layer3(const float* hbuf, const float* W3s,
                                            int tid)
{
    constexpr int ST = TM + 4;
    const int row = tid >> 2;
    const int qt  = tid & 3;
    float y = 0.f;
    if (row < TM) {
        const float* col = hbuf + qt * 16 * ST + row;
        const float* w   = W3s + qt * 16;
        #pragma unroll 8
        for (int c = 0; c < 16; c++)
            y = fmaf(col[c * ST], w[c], y);
    }
    y += __shfl_xor_sync(0xffffffffu, y, 1);
    y += __shfl_xor_sync(0xffffffffu, y, 2);
    return y;   // valid for qt==0, row<TM
}

// vectorized weight staging (all pointers 16B aligned)
__device__ __forceinline__ void stage_weights(float* W1s, float* b1s,
                                              float* W2s, float* b2s,
                                              float* W3s, float* b3s,
                                              const float* W1, const float* b1,
                                              const float* W2, const float* b2,
                                              const float* W3, const float* b3,
                                              int tid)
{
    const float4* W1v = (const float4*)W1;
    const float4* W2v = (const float4*)W2;
    float4* W1sv = (float4*)W1s;
    float4* W2sv = (float4*)W2s;
    for (int i = tid; i < K1 * HDIM / 4; i += 256)   W1sv[i] = W1v[i];
    for (int i = tid; i < HDIM * HDIM / 4; i += 256) W2sv[i] = W2v[i];
    if (tid < HDIM) {
        b1s[tid] = b1[tid];
        b2s[tid] = b2[tid];
        W3s[tid] = W3[tid];
    }
    if (tid == 0) b3s[0] = b3[0];
}

// ---------------- big levels (l >= 6): one launch per level ----------------
template <int TM>
__global__ void __launch_bounds__(256, 3)
level_kernel(const float* __restrict__ features,
             const float* __restrict__ treatment,
             float* __restrict__ out,
             const float* __restrict__ W1, const float* __restrict__ b1,
             const float* __restrict__ W2, const float* __restrict__ b2,
             const float* __restrict__ W3, const float* __restrict__ b3,
             int lshift, int leaf)
{
    constexpr int ST = TM + 4;
    const int n     = 1 << lshift;
    const int start = n - 1;

    extern __shared__ float sm[];
    float* W1s  = sm;
    float* b1s  = W1s + K1 * HDIM;
    float* W2s  = b1s + HDIM;
    float* b2s  = W2s + HDIM * HDIM;
    float* W3s  = b2s + HDIM;
    float* b3s  = W3s + HDIM;
    float* xbuf = sm + WOFF;
    float* hbuf = xbuf + K1 * ST;

    const int tid = threadIdx.x;

    stage_weights(W1s, b1s, W2s, b2s, W3s, b3s,
                  W1, b1, W2, b2, W3, b3, tid);

    const int row0 = blockIdx.x * TM;
    for (int i = tid; i < TM * (FDIM / 4); i += 256) {
        int r = i >> 3;
        int q = i & 7;
        int g = row0 + r;
        int b = g >> lshift;
        int node = g & (n - 1);
        float4 v = *(const float4*)
            (features + ((size_t)b * NNODES + start + node) * FDIM + 4 * q);
        xbuf[(4 * q + 0) * ST + r] = v.x;
        xbuf[(4 * q + 1) * ST + r] = v.y;
        xbuf[(4 * q + 2) * ST + r] = v.z;
        xbuf[(4 * q + 3) * ST + r] = v.w;
    }
    if (tid < TM) {
        int g = row0 + tid;
        int b = g >> lshift;
        int node = g & (n - 1);
        float lv = 0.f, rv = 0.f;
        if (!leaf) {
            const float* c = out + (size_t)b * NNODES + (2 * n - 1) + 2 * node;
            lv = c[0];
            rv = c[1];
        }
        xbuf[32 * ST + tid] = lv;
        xbuf[33 * ST + tid] = rv;
        xbuf[34 * ST + tid] = treatment[b];
    }
    __syncthreads();

    mlp_layers12<TM>(xbuf, hbuf, W1s, b1s, W2s, b2s, tid);

    float y = mlp_layer3<TM>(hbuf, W3s, tid);
    const int row = tid >> 2;
    if ((tid & 3) == 0 && row < TM) {
        int g = row0 + row;
        int b = g >> lshift;
        int node = g & (n - 1);
        out[(size_t)b * NNODES + start + node] = y + b3s[0];
    }
}

// ------------- tail levels (l = 5..0): one launch, 512 blocks -------------
__global__ void __launch_bounds__(256, 3)
tail_kernel(const float* __restrict__ features,
            const float* __restrict__ treatment,
            float* __restrict__ out,
            const float* __restrict__ W1, const float* __restrict__ b1,
            const float* __restrict__ W2, const float* __restrict__ b2,
            const float* __restrict__ W3, const float* __restrict__ b3)
{
    constexpr int TM = 32;
    constexpr int ST = TM + 4;

    extern __shared__ float sm[];
    float* W1s  = sm;
    float* b1s  = W1s + K1 * HDIM;
    float* W2s  = b1s + HDIM;
    float* b2s  = W2s + HDIM * HDIM;
    float* W3s  = b2s + HDIM;
    float* b3s  = W3s + HDIM;
    float* xbuf = sm + WOFF;
    float* hbuf = xbuf + K1 * ST;
    float* ybuf = hbuf + HDIM * ST;   // 66 floats: child values

    const int tid = threadIdx.x;
    const int b   = blockIdx.x;
    const float tval = treatment[b];

    // preload level-6 outputs (children of level 5): out[b*2047 + 63..126]
    if (tid < 64)
        ybuf[tid] = out[(size_t)b * NNODES + 63 + tid];

    for (int l = 5; l >= 0; --l) {
        const int n     = 1 << l;
        const int start = n - 1;

        __syncthreads();   // prior level fully done (ybuf, weight reads)

        stage_weights(W1s, b1s, W2s, b2s, W3s, b3s,
                      W1 + (size_t)l * K1 * HDIM, b1 + (size_t)l * HDIM,
                      W2 + (size_t)l * HDIM * HDIM, b2 + (size_t)l * HDIM,
                      W3 + (size_t)l * HDIM, b3 + (size_t)l, tid);

        for (int i = tid; i < n * (FDIM / 4); i += 256) {
            int r = i >> 3;
            int q = i & 7;
            float4 v = *(const float4*)
                (features + ((size_t)b * NNODES + start + r) * FDIM + 4 * q);
            xbuf[(4 * q + 0) * ST + r] = v.x;
            xbuf[(4 * q + 1) * ST + r] = v.y;
            xbuf[(4 * q + 2) * ST + r] = v.z;
            xbuf[(4 * q + 3) * ST + r] = v.w;
        }
        if (tid < n) {
            xbuf[32 * ST + tid] = ybuf[2 * tid];
            xbuf[33 * ST + tid] = ybuf[2 * tid + 1];
            xbuf[34 * ST + tid] = tval;
        }
        __syncthreads();

        mlp_layers12<TM>(xbuf, hbuf, W1s, b1s, W2s, b2s, tid);

        float y = mlp_layer3<TM>(hbuf, W3s, tid);
        const int row = tid >> 2;
        if ((tid & 3) == 0 && row < n) {
            float yo = y + b3s[0];
            ybuf[row] = yo;
            out[(size_t)b * NNODES + start + row] = yo;
        }
    }
}

extern "C" void kernel_launch(void* const* d_in, const int* in_sizes, int n_in,
                              void* d_out, int out_size)
{
    const float* features  = (const float*)d_in[0];
    const float* treatment = (const float*)d_in[1];
    const float* W1 = (const float*)d_in[2];
    const float* b1 = (const float*)d_in[3];
    const float* W2 = (const float*)d_in[4];
    const float* b2 = (const float*)d_in[5];
    const float* W3 = (const float*)d_in[6];
    const float* b3 = (const float*)d_in[7];
    float* out = (float*)d_out;

    // TM=64, ST=68: 6536 + 35*68 + 64*68 = 13268 floats = 53,072 B (3 CTAs/SM)
    const int smem64   = (WOFF + K1 * 68 + HDIM * 68) * 4;
    // tail TM=32, ST=36: 6536 + 35*36 + 64*36 + 66 = 10166 floats = 40,664 B
    const int smemTail = (WOFF + K1 * 36 + HDIM * 36 + 66) * 4;
    cudaFuncSetAttribute(level_kernel<64>,
                         cudaFuncAttributeMaxDynamicSharedMemorySize, smem64);
    cudaFuncSetAttribute(tail_kernel,
                         cudaFuncAttributeMaxDynamicSharedMemorySize, smemTail);

    for (int l = DLEV - 1; l >= 6; --l) {
        const int rows = BATCH << l;
        const int leaf = (l == DLEV - 1) ? 1 : 0;
        level_kernel<64><<<rows / 64, 256, smem64>>>(
            features, treatment, out,
            W1 + (size_t)l * K1 * HDIM, b1 + (size_t)l * HDIM,
            W2 + (size_t)l * HDIM * HDIM, b2 + (size_t)l * HDIM,
            W3 + (size_t)l * HDIM, b3 + (size_t)l,
            l, leaf);
    }
    tail_kernel<<<BATCH, 256, smemTail>>>(
        features, treatment, out, W1, b1, W2, b2, W3, b3);
}